// round 3
// baseline (speedup 1.0000x reference)
#include <cuda_runtime.h>
#include <cuda_bf16.h>
#include <math.h>

// Problem constants
#define Bc 2
#define Sc 2048
#define Cc 1280
#define Hc 20
#define Dc 64
#define Rc 16
#define Mrows (Bc*Sc)          // 4096
#define QSCALE 0.125f          // 1/sqrt(64)

// ------------------------- device scratch (no allocs allowed) ---------------
__device__ float g_Wq[Cc*Cc];
__device__ float g_Wk[Cc*Cc];
__device__ float g_Wv[Cc*Cc];
__device__ float g_Wo[Cc*Cc];
__device__ float g_q[Mrows*Cc];
__device__ float g_k[Mrows*Cc];
__device__ float g_v[Mrows*Cc];
__device__ float g_oacc[Mrows*Cc];

// ------------------------- tf32 helpers -------------------------------------
__device__ __forceinline__ unsigned f2tf32(float f) {
    unsigned u;
    asm("cvt.rna.tf32.f32 %0, %1;" : "=r"(u) : "f"(f));
    return u;
}

// D += A * B, m16n8k8, A row-major tf32, B col-major tf32, fp32 accum
__device__ __forceinline__ void mma_tf32(float* d, const unsigned* a, const unsigned* b) {
    asm("mma.sync.aligned.m16n8k8.row.col.f32.tf32.tf32.f32 "
        "{%0,%1,%2,%3}, {%4,%5,%6,%7}, {%8,%9}, {%0,%1,%2,%3};"
        : "+f"(d[0]), "+f"(d[1]), "+f"(d[2]), "+f"(d[3])
        : "r"(a[0]), "r"(a[1]), "r"(a[2]), "r"(a[3]), "r"(b[0]), "r"(b[1]));
}

// ------------------------- fuse LoRA into dense weights (all 4 at once) -----
__global__ void fuse_all_kernel(
    const float* __restrict__ Wq, const float* __restrict__ Aq, const float* __restrict__ Bq,
    const float* __restrict__ Wk, const float* __restrict__ Ak, const float* __restrict__ Bk,
    const float* __restrict__ Wv, const float* __restrict__ Av, const float* __restrict__ Bv,
    const float* __restrict__ Wo, const float* __restrict__ Ao, const float* __restrict__ Bo,
    float* __restrict__ oq, float* __restrict__ ok,
    float* __restrict__ ov, float* __restrict__ oo) {
    int idx = blockIdx.x * blockDim.x + threadIdx.x;
    if (idx >= Cc*Cc) return;
    const float *W, *A, *Bup; float* out;
    switch (blockIdx.y) {
        case 0: W = Wq; A = Aq; Bup = Bq; out = oq; break;
        case 1: W = Wk; A = Ak; Bup = Bk; out = ok; break;
        case 2: W = Wv; A = Av; Bup = Bv; out = ov; break;
        default: W = Wo; A = Ao; Bup = Bo; out = oo; break;
    }
    int o = idx / Cc;
    int c = idx - o * Cc;
    float acc = W[idx];
#pragma unroll
    for (int r = 0; r < Rc; r++)
        acc += Bup[o*Rc + r] * A[r*Cc + c];
    out[idx] = acc;
}

// ------------------------- tf32 GEMM: Y = X @ W^T (+bias) -------------------
// Block tile 128x128, BK=32, 256 threads (8 warps, 2m x 4n), warp tile 64x32.
// smem stride 40 (== 8 mod 32): permuted cols so fragment pairs (t,t+4) are
// adjacent -> conflict-free uint2 loads.
#define XST 40
__global__ __launch_bounds__(256) void gemm_tf32_kernel(
    const float* __restrict__ X,
    const float* __restrict__ W0, const float* __restrict__ W1, const float* __restrict__ W2,
    const float* __restrict__ bias,
    float* __restrict__ Y0, float* __restrict__ Y1, float* __restrict__ Y2,
    int M, int N, int K) {
    __shared__ unsigned Xs[128 * XST];
    __shared__ unsigned Ws[128 * XST];

    const float* W = (blockIdx.z == 0) ? W0 : (blockIdx.z == 1) ? W1 : W2;
    float* Y       = (blockIdx.z == 0) ? Y0 : (blockIdx.z == 1) ? Y1 : Y2;

    int tid = threadIdx.x;
    int lane = tid & 31, wid = tid >> 5;
    int g = lane >> 2, t = lane & 3;
    int wm = wid & 1, wn = wid >> 1;           // warp coords: 2 x 4
    int m0 = blockIdx.y * 128, n0 = blockIdx.x * 128;

    float acc[4][4][4];
#pragma unroll
    for (int i = 0; i < 4; i++)
#pragma unroll
        for (int j = 0; j < 4; j++)
#pragma unroll
            for (int u = 0; u < 4; u++) acc[i][j][u] = 0.f;

    for (int k0 = 0; k0 < K; k0 += 32) {
        // load 128x32 tiles; convert to tf32; permuted column scatter:
        // logical col c in 8-group stored at 2*(c&3) + (c>>2 & 1)
#pragma unroll
        for (int e = tid; e < 128 * 8; e += 256) {
            int r = e >> 3, c4 = (e & 7) << 2;
            int kb = c4 & 24, half = (c4 >> 2) & 1;
            float4 xv = *(const float4*)&X[(size_t)(m0 + r) * K + k0 + c4];
            unsigned* p = &Xs[r * XST + kb + half];
            p[0] = f2tf32(xv.x); p[2] = f2tf32(xv.y);
            p[4] = f2tf32(xv.z); p[6] = f2tf32(xv.w);
            float4 wv = *(const float4*)&W[(size_t)(n0 + r) * K + k0 + c4];
            unsigned* q = &Ws[r * XST + kb + half];
            q[0] = f2tf32(wv.x); q[2] = f2tf32(wv.y);
            q[4] = f2tf32(wv.z); q[6] = f2tf32(wv.w);
        }
        __syncthreads();

#pragma unroll
        for (int kc = 0; kc < 4; kc++) {
            int kb = kc * 8;
            unsigned a[4][4], b[4][2];
#pragma unroll
            for (int mt = 0; mt < 4; mt++) {
                int rb = wm * 64 + mt * 16;
                uint2 lo = *(uint2*)&Xs[(rb + g)     * XST + kb + 2*t];
                uint2 hi = *(uint2*)&Xs[(rb + g + 8) * XST + kb + 2*t];
                a[mt][0] = lo.x; a[mt][1] = hi.x; a[mt][2] = lo.y; a[mt][3] = hi.y;
            }
#pragma unroll
            for (int nt = 0; nt < 4; nt++) {
                int nb = wn * 32 + nt * 8;
                uint2 bu = *(uint2*)&Ws[(nb + g) * XST + kb + 2*t];
                b[nt][0] = bu.x; b[nt][1] = bu.y;
            }
#pragma unroll
            for (int mt = 0; mt < 4; mt++)
#pragma unroll
                for (int nt = 0; nt < 4; nt++)
                    mma_tf32(acc[mt][nt], a[mt], b[nt]);
        }
        __syncthreads();
    }

#pragma unroll
    for (int mt = 0; mt < 4; mt++) {
        int row = m0 + wm * 64 + mt * 16 + g;
#pragma unroll
        for (int nt = 0; nt < 4; nt++) {
            int col = n0 + wn * 32 + nt * 8 + 2 * t;
            float b0 = bias ? bias[col] : 0.f;
            float b1 = bias ? bias[col + 1] : 0.f;
            float2 v0 = make_float2(acc[mt][nt][0] + b0, acc[mt][nt][1] + b1);
            float2 v1 = make_float2(acc[mt][nt][2] + b0, acc[mt][nt][3] + b1);
            *(float2*)&Y[(size_t)row * N + col] = v0;
            *(float2*)&Y[(size_t)(row + 8) * N + col] = v1;
        }
    }
}

// ------------------------- tf32 flash attention ------------------------------
// grid (S/128, H, B) = (16,20,2); 128 threads = 4 warps; warp owns 32 q-rows
// (two m16 tiles). K tile 64 keys. Q/K/P smem permuted cols (uint2 frags);
// V row-major (scalar frags, conflict-free).
#define FST 72
#define FLASH_SMEM ((128*FST + 64*FST + 64*FST + 128*FST) * 4)

__global__ __launch_bounds__(128) void flash_tf32_kernel(
    const float* __restrict__ Qg, const float* __restrict__ Kg,
    const float* __restrict__ Vg, float* __restrict__ Og) {
    extern __shared__ unsigned sm[];
    unsigned* Qs = sm;                    // 128 x 72 (permuted)
    unsigned* Ks = Qs + 128 * FST;        // 64 x 72 (permuted)
    unsigned* Vs = Ks + 64 * FST;         // 64 x 72 (straight)
    unsigned* Ps = Vs + 64 * FST;         // 128 x 72 (permuted)

    int tid = threadIdx.x;
    int lane = tid & 31, wid = tid >> 5;
    int g = lane >> 2, t = lane & 3;
    int wq = wid * 32;
    int qt = blockIdx.x, h = blockIdx.y, b = blockIdx.z;

    const float* Qp = Qg + (size_t)(b * Sc + qt * 128) * Cc + h * Dc;
    const float* Kp = Kg + (size_t)b * Sc * Cc + h * Dc;
    const float* Vp = Vg + (size_t)b * Sc * Cc + h * Dc;

    // stage Q (128x64) permuted
#pragma unroll
    for (int e = tid; e < 128 * 16; e += 128) {
        int r = e >> 4, c4 = (e & 15) << 2;
        int kb = c4 & 56, half = (c4 >> 2) & 1;
        float4 v = *(const float4*)&Qp[(size_t)r * Cc + c4];
        unsigned* p = &Qs[r * FST + kb + half];
        p[0] = f2tf32(v.x); p[2] = f2tf32(v.y);
        p[4] = f2tf32(v.z); p[6] = f2tf32(v.w);
    }
    __syncthreads();

    // physical P-write columns for logical (2t, 2t+1)
    int p0 = (t & 1) * 4 + (t >> 1);   // phys(2t):   0,4,1,5
    int p1 = p0 + 2;                   // phys(2t+1): 2,6,3,7

    float mrow[2][2], lrow[2][2];
#pragma unroll
    for (int mt = 0; mt < 2; mt++) { mrow[mt][0] = mrow[mt][1] = -INFINITY;
                                     lrow[mt][0] = lrow[mt][1] = 0.f; }
    float oacc[2][8][4];
#pragma unroll
    for (int mt = 0; mt < 2; mt++)
#pragma unroll
        for (int dt = 0; dt < 8; dt++)
#pragma unroll
            for (int u = 0; u < 4; u++) oacc[mt][dt][u] = 0.f;

    for (int kt = 0; kt < Sc / 64; kt++) {
        // load K (permuted) and V (straight)
#pragma unroll
        for (int e = tid; e < 64 * 16; e += 128) {
            int r = e >> 4, c4 = (e & 15) << 2;
            int kb = c4 & 56, half = (c4 >> 2) & 1;
            float4 kv = *(const float4*)&Kp[(size_t)(kt * 64 + r) * Cc + c4];
            unsigned* pk = &Ks[r * FST + kb + half];
            pk[0] = f2tf32(kv.x); pk[2] = f2tf32(kv.y);
            pk[4] = f2tf32(kv.z); pk[6] = f2tf32(kv.w);
            float4 vv = *(const float4*)&Vp[(size_t)(kt * 64 + r) * Cc + c4];
            unsigned* pv = &Vs[r * FST + c4];
            pv[0] = f2tf32(vv.x); pv[1] = f2tf32(vv.y);
            pv[2] = f2tf32(vv.z); pv[3] = f2tf32(vv.w);
        }
        __syncthreads();

        // S = Q K^T : per warp m32 x n64, k=64
        float sacc[2][8][4];
#pragma unroll
        for (int mt = 0; mt < 2; mt++)
#pragma unroll
            for (int nt = 0; nt < 8; nt++)
#pragma unroll
                for (int u = 0; u < 4; u++) sacc[mt][nt][u] = 0.f;

#pragma unroll
        for (int kc = 0; kc < 8; kc++) {
            int kb = kc * 8;
            unsigned qa[2][4];
#pragma unroll
            for (int mt = 0; mt < 2; mt++) {
                uint2 lo = *(uint2*)&Qs[(wq + mt*16 + g)     * FST + kb + 2*t];
                uint2 hi = *(uint2*)&Qs[(wq + mt*16 + g + 8) * FST + kb + 2*t];
                qa[mt][0] = lo.x; qa[mt][1] = hi.x; qa[mt][2] = lo.y; qa[mt][3] = hi.y;
            }
#pragma unroll
            for (int nt = 0; nt < 8; nt++) {
                uint2 bu = *(uint2*)&Ks[(nt * 8 + g) * FST + kb + 2*t];
                unsigned bb[2] = {bu.x, bu.y};
                mma_tf32(sacc[0][nt], qa[0], bb);
                mma_tf32(sacc[1][nt], qa[1], bb);
            }
        }

        // online softmax: per m-tile, rows r=0 (g) and r=1 (g+8)
#pragma unroll
        for (int mt = 0; mt < 2; mt++) {
#pragma unroll
            for (int r = 0; r < 2; r++) {
                float mloc = -INFINITY;
#pragma unroll
                for (int nt = 0; nt < 8; nt++)
                    mloc = fmaxf(mloc, fmaxf(sacc[mt][nt][2*r], sacc[mt][nt][2*r+1]));
                mloc = fmaxf(mloc, __shfl_xor_sync(0xffffffffu, mloc, 1));
                mloc = fmaxf(mloc, __shfl_xor_sync(0xffffffffu, mloc, 2));
                float mnew = fmaxf(mrow[mt][r], mloc * QSCALE);
                float alpha = __expf(mrow[mt][r] - mnew);
                float sum = 0.f;
#pragma unroll
                for (int nt = 0; nt < 8; nt++) {
#pragma unroll
                    for (int j = 0; j < 2; j++) {
                        float p = __expf(sacc[mt][nt][2*r+j] * QSCALE - mnew);
                        sacc[mt][nt][2*r+j] = p;
                        sum += p;
                    }
                }
                sum += __shfl_xor_sync(0xffffffffu, sum, 1);
                sum += __shfl_xor_sync(0xffffffffu, sum, 2);
                lrow[mt][r] = lrow[mt][r] * alpha + sum;
                mrow[mt][r] = mnew;
#pragma unroll
                for (int dt = 0; dt < 8; dt++) {
                    oacc[mt][dt][2*r]   *= alpha;
                    oacc[mt][dt][2*r+1] *= alpha;
                }
            }
        }

        // write P (permuted) — warp-local rows only
#pragma unroll
        for (int mt = 0; mt < 2; mt++) {
            int r0 = wq + mt * 16 + g, r1 = r0 + 8;
#pragma unroll
            for (int nt = 0; nt < 8; nt++) {
                Ps[r0 * FST + nt*8 + p0] = f2tf32(sacc[mt][nt][0]);
                Ps[r0 * FST + nt*8 + p1] = f2tf32(sacc[mt][nt][1]);
                Ps[r1 * FST + nt*8 + p0] = f2tf32(sacc[mt][nt][2]);
                Ps[r1 * FST + nt*8 + p1] = f2tf32(sacc[mt][nt][3]);
            }
        }
        __syncwarp();

        // O += P V : per warp m32 x n64(d), k=64(keys)
#pragma unroll
        for (int kc = 0; kc < 8; kc++) {
            int kb = kc * 8;
            unsigned pa[2][4];
#pragma unroll
            for (int mt = 0; mt < 2; mt++) {
                uint2 lo = *(uint2*)&Ps[(wq + mt*16 + g)     * FST + kb + 2*t];
                uint2 hi = *(uint2*)&Ps[(wq + mt*16 + g + 8) * FST + kb + 2*t];
                pa[mt][0] = lo.x; pa[mt][1] = hi.x; pa[mt][2] = lo.y; pa[mt][3] = hi.y;
            }
#pragma unroll
            for (int dt = 0; dt < 8; dt++) {
                unsigned bb[2];
                bb[0] = Vs[(kb + t)     * FST + dt*8 + g];
                bb[1] = Vs[(kb + t + 4) * FST + dt*8 + g];
                mma_tf32(oacc[0][dt], pa[0], bb);
                mma_tf32(oacc[1][dt], pa[1], bb);
            }
        }
        __syncthreads();   // before next tile overwrites Ks/Vs
    }

    // epilogue
#pragma unroll
    for (int mt = 0; mt < 2; mt++) {
#pragma unroll
        for (int r = 0; r < 2; r++) {
            float inv = 1.f / lrow[mt][r];
            int grow = b * Sc + qt * 128 + wq + mt*16 + g + 8*r;
#pragma unroll
            for (int dt = 0; dt < 8; dt++) {
                int col = h * Dc + dt * 8 + 2 * t;
                float2 v = make_float2(oacc[mt][dt][2*r] * inv,
                                       oacc[mt][dt][2*r+1] * inv);
                *(float2*)&Og[(size_t)grow * Cc + col] = v;
            }
        }
    }
}

// ------------------------- launch -------------------------------------------
extern "C" void kernel_launch(void* const* d_in, const int* in_sizes, int n_in,
                              void* d_out, int out_size) {
    const float* x  = (const float*)d_in[0];
    const float* Wq = (const float*)d_in[1];
    const float* Wk = (const float*)d_in[2];
    const float* Wv = (const float*)d_in[3];
    const float* Wo = (const float*)d_in[4];
    const float* bo = (const float*)d_in[5];
    const float* Aq = (const float*)d_in[6];
    const float* Bq = (const float*)d_in[7];
    const float* Ak = (const float*)d_in[8];
    const float* Bk = (const float*)d_in[9];
    const float* Av = (const float*)d_in[10];
    const float* Bv = (const float*)d_in[11];
    const float* Ao = (const float*)d_in[12];
    const float* Bo = (const float*)d_in[13];
    float* out = (float*)d_out;

    float *pWq, *pWk, *pWv, *pWo, *pq, *pk, *pv, *po;
    cudaGetSymbolAddress((void**)&pWq, g_Wq);
    cudaGetSymbolAddress((void**)&pWk, g_Wk);
    cudaGetSymbolAddress((void**)&pWv, g_Wv);
    cudaGetSymbolAddress((void**)&pWo, g_Wo);
    cudaGetSymbolAddress((void**)&pq, g_q);
    cudaGetSymbolAddress((void**)&pk, g_k);
    cudaGetSymbolAddress((void**)&pv, g_v);
    cudaGetSymbolAddress((void**)&po, g_oacc);

    // 1) fold LoRA into dense weights
    dim3 fgrid((Cc * Cc + 255) / 256, 4);
    fuse_all_kernel<<<fgrid, 256>>>(Wq, Aq, Bq, Wk, Ak, Bk, Wv, Av, Bv, Wo, Ao, Bo,
                                    pWq, pWk, pWv, pWo);

    // 2) q/k/v projections in one launch
    dim3 ggrid(Cc / 128, Mrows / 128, 3);
    gemm_tf32_kernel<<<ggrid, 256>>>(x, pWq, pWk, pWv, nullptr, pq, pk, pv,
                                     Mrows, Cc, Cc);

    // 3) flash attention
    cudaFuncSetAttribute(flash_tf32_kernel,
                         cudaFuncAttributeMaxDynamicSharedMemorySize, FLASH_SMEM);
    dim3 agrid(Sc / 128, Hc, Bc);           // (16, 20, 2)
    flash_tf32_kernel<<<agrid, 128, FLASH_SMEM>>>(pq, pk, pv, po);

    // 4) output projection (+bias) -> d_out
    dim3 ogrid(Cc / 128, Mrows / 128, 1);
    gemm_tf32_kernel<<<ogrid, 256>>>(po, pWo, pWo, pWo, bo, out, out, out,
                                     Mrows, Cc, Cc);
}

// round 4
// speedup vs baseline: 1.1211x; 1.1211x over previous
#include <cuda_runtime.h>
#include <cuda_bf16.h>
#include <math.h>

// Problem constants
#define Bc 2
#define Sc 2048
#define Cc 1280
#define Hc 20
#define Dc 64
#define Rc 16
#define Mrows (Bc*Sc)          // 4096
#define QSCALE 0.125f          // 1/sqrt(64)

// ------------------------- device scratch (no allocs allowed) ---------------
__device__ float g_Wq[Cc*Cc];
__device__ float g_Wk[Cc*Cc];
__device__ float g_Wv[Cc*Cc];
__device__ float g_Wo[Cc*Cc];
__device__ float g_q[Mrows*Cc];
__device__ float g_k[Mrows*Cc];
__device__ float g_v[Mrows*Cc];
__device__ float g_oacc[Mrows*Cc];

// ------------------------- tf32 helpers -------------------------------------
__device__ __forceinline__ unsigned f2tf32(float f) {
    unsigned u;
    asm("cvt.rna.tf32.f32 %0, %1;" : "=r"(u) : "f"(f));
    return u;
}

__device__ __forceinline__ void mma_tf32(float* d, const unsigned* a, const unsigned* b) {
    asm("mma.sync.aligned.m16n8k8.row.col.f32.tf32.tf32.f32 "
        "{%0,%1,%2,%3}, {%4,%5,%6,%7}, {%8,%9}, {%0,%1,%2,%3};"
        : "+f"(d[0]), "+f"(d[1]), "+f"(d[2]), "+f"(d[3])
        : "r"(a[0]), "r"(a[1]), "r"(a[2]), "r"(a[3]), "r"(b[0]), "r"(b[1]));
}

// ------------------------- fuse LoRA into dense weights (all 4 at once) -----
__global__ void fuse_all_kernel(
    const float* __restrict__ Wq, const float* __restrict__ Aq, const float* __restrict__ Bq,
    const float* __restrict__ Wk, const float* __restrict__ Ak, const float* __restrict__ Bk,
    const float* __restrict__ Wv, const float* __restrict__ Av, const float* __restrict__ Bv,
    const float* __restrict__ Wo, const float* __restrict__ Ao, const float* __restrict__ Bo,
    float* __restrict__ oq, float* __restrict__ ok,
    float* __restrict__ ov, float* __restrict__ oo) {
    int idx = blockIdx.x * blockDim.x + threadIdx.x;
    if (idx >= Cc*Cc) return;
    const float *W, *A, *Bup; float* out;
    switch (blockIdx.y) {
        case 0: W = Wq; A = Aq; Bup = Bq; out = oq; break;
        case 1: W = Wk; A = Ak; Bup = Bk; out = ok; break;
        case 2: W = Wv; A = Av; Bup = Bv; out = ov; break;
        default: W = Wo; A = Ao; Bup = Bo; out = oo; break;
    }
    int o = idx / Cc;
    int c = idx - o * Cc;
    float acc = W[idx];
#pragma unroll
    for (int r = 0; r < Rc; r++)
        acc += Bup[o*Rc + r] * A[r*Cc + c];
    out[idx] = acc;
}

// ------------------------- tf32 GEMM: Y = X @ W^T (+bias) -------------------
// (R2 version — fastest measured). 128x128 tile, BK=32, 256 thr, warp 64x32.
#define XST 36
__global__ __launch_bounds__(256) void gemm_tf32_kernel(
    const float* __restrict__ X,
    const float* __restrict__ W0, const float* __restrict__ W1, const float* __restrict__ W2,
    const float* __restrict__ bias,
    float* __restrict__ Y0, float* __restrict__ Y1, float* __restrict__ Y2,
    int M, int N, int K) {
    __shared__ unsigned Xs[128 * XST];
    __shared__ unsigned Ws[128 * XST];

    const float* W = (blockIdx.z == 0) ? W0 : (blockIdx.z == 1) ? W1 : W2;
    float* Y       = (blockIdx.z == 0) ? Y0 : (blockIdx.z == 1) ? Y1 : Y2;

    int tid = threadIdx.x;
    int lane = tid & 31, wid = tid >> 5;
    int g = lane >> 2, t = lane & 3;
    int wm = wid & 1, wn = wid >> 1;
    int m0 = blockIdx.y * 128, n0 = blockIdx.x * 128;

    float acc[4][4][4];
#pragma unroll
    for (int i = 0; i < 4; i++)
#pragma unroll
        for (int j = 0; j < 4; j++)
#pragma unroll
            for (int u = 0; u < 4; u++) acc[i][j][u] = 0.f;

    for (int k0 = 0; k0 < K; k0 += 32) {
#pragma unroll
        for (int e = tid; e < 128 * 8; e += 256) {
            int r = e >> 3, c4 = (e & 7) << 2;
            float4 xv = *(const float4*)&X[(size_t)(m0 + r) * K + k0 + c4];
            unsigned* p = &Xs[r * XST + c4];
            p[0] = f2tf32(xv.x); p[1] = f2tf32(xv.y);
            p[2] = f2tf32(xv.z); p[3] = f2tf32(xv.w);
            float4 wv = *(const float4*)&W[(size_t)(n0 + r) * K + k0 + c4];
            unsigned* q = &Ws[r * XST + c4];
            q[0] = f2tf32(wv.x); q[1] = f2tf32(wv.y);
            q[2] = f2tf32(wv.z); q[3] = f2tf32(wv.w);
        }
        __syncthreads();

#pragma unroll
        for (int kc = 0; kc < 4; kc++) {
            int kb = kc * 8;
            unsigned a[4][4], b[4][2];
#pragma unroll
            for (int mt = 0; mt < 4; mt++) {
                int rb = wm * 64 + mt * 16;
                a[mt][0] = Xs[(rb + g)     * XST + kb + t];
                a[mt][1] = Xs[(rb + g + 8) * XST + kb + t];
                a[mt][2] = Xs[(rb + g)     * XST + kb + t + 4];
                a[mt][3] = Xs[(rb + g + 8) * XST + kb + t + 4];
            }
#pragma unroll
            for (int nt = 0; nt < 4; nt++) {
                int nb = wn * 32 + nt * 8;
                b[nt][0] = Ws[(nb + g) * XST + kb + t];
                b[nt][1] = Ws[(nb + g) * XST + kb + t + 4];
            }
#pragma unroll
            for (int mt = 0; mt < 4; mt++)
#pragma unroll
                for (int nt = 0; nt < 4; nt++)
                    mma_tf32(acc[mt][nt], a[mt], b[nt]);
        }
        __syncthreads();
    }

#pragma unroll
    for (int mt = 0; mt < 4; mt++) {
        int row = m0 + wm * 64 + mt * 16 + g;
#pragma unroll
        for (int nt = 0; nt < 4; nt++) {
            int col = n0 + wn * 32 + nt * 8 + 2 * t;
            float b0 = bias ? bias[col] : 0.f;
            float b1 = bias ? bias[col + 1] : 0.f;
            float2 v0 = make_float2(acc[mt][nt][0] + b0, acc[mt][nt][1] + b1);
            float2 v1 = make_float2(acc[mt][nt][2] + b0, acc[mt][nt][3] + b1);
            *(float2*)&Y[(size_t)row * N + col] = v0;
            *(float2*)&Y[(size_t)(row + 8) * N + col] = v1;
        }
    }
}

// ------------------------- tf32 flash attention ------------------------------
// grid (S/128, H, B) = (16,20,2); 256 threads = 8 warps; warp owns 16 q-rows.
// Q fragments resident in registers (loaded once); P buffer aliases Q staging.
// smem = K(64x72 permuted) + V(64x72 straight) + P(128x72 permuted) = 73.7KB.
#define FST 72
#define FLASH_SMEM ((64*FST + 64*FST + 128*FST) * 4)

__global__ __launch_bounds__(256, 2) void flash_tf32_kernel(
    const float* __restrict__ Qg, const float* __restrict__ Kg,
    const float* __restrict__ Vg, float* __restrict__ Og) {
    extern __shared__ unsigned sm[];
    unsigned* Ks = sm;                    // 64 x 72 (permuted)
    unsigned* Vs = Ks + 64 * FST;         // 64 x 72 (straight)
    unsigned* Ps = Vs + 64 * FST;         // 128 x 72 (permuted; Q staging first)

    int tid = threadIdx.x;
    int lane = tid & 31, wid = tid >> 5;   // wid 0..7
    int g = lane >> 2, t = lane & 3;
    int wq = wid * 16;
    int qt = blockIdx.x, h = blockIdx.y, b = blockIdx.z;

    const float* Qp = Qg + (size_t)(b * Sc + qt * 128) * Cc + h * Dc;
    const float* Kp = Kg + (size_t)b * Sc * Cc + h * Dc;
    const float* Vp = Vg + (size_t)b * Sc * Cc + h * Dc;

    // ---- prologue: stage Q (128x64) permuted into Ps, then lift to registers
#pragma unroll
    for (int e = tid; e < 128 * 16; e += 256) {
        int r = e >> 4, c4 = (e & 15) << 2;
        int kb = c4 & 56, half = (c4 >> 2) & 1;
        float4 v = *(const float4*)&Qp[(size_t)r * Cc + c4];
        unsigned* p = &Ps[r * FST + kb + half];
        p[0] = f2tf32(v.x); p[2] = f2tf32(v.y);
        p[4] = f2tf32(v.z); p[6] = f2tf32(v.w);
    }
    __syncthreads();

    unsigned qa[8][4];
#pragma unroll
    for (int kc = 0; kc < 8; kc++) {
        int kb = kc * 8;
        uint2 lo = *(uint2*)&Ps[(wq + g)     * FST + kb + 2*t];
        uint2 hi = *(uint2*)&Ps[(wq + g + 8) * FST + kb + 2*t];
        qa[kc][0] = lo.x; qa[kc][1] = hi.x; qa[kc][2] = lo.y; qa[kc][3] = hi.y;
    }
    __syncthreads();   // Ps free for P use

    // physical P-write columns for logical (2t, 2t+1)
    int p0 = (t & 1) * 4 + (t >> 1);
    int p1 = p0 + 2;

    float mrow[2] = {-INFINITY, -INFINITY};
    float lrow[2] = {0.f, 0.f};
    float oacc[8][4];
#pragma unroll
    for (int dt = 0; dt < 8; dt++)
#pragma unroll
        for (int u = 0; u < 4; u++) oacc[dt][u] = 0.f;

    for (int kt = 0; kt < Sc / 64; kt++) {
        // ---- fill K (permuted scatter) and V (straight, vectorized)
#pragma unroll
        for (int e = tid; e < 64 * 16; e += 256) {
            int r = e >> 4, c4 = (e & 15) << 2;
            int kb = c4 & 56, half = (c4 >> 2) & 1;
            float4 kv = *(const float4*)&Kp[(size_t)(kt * 64 + r) * Cc + c4];
            unsigned* pk = &Ks[r * FST + kb + half];
            pk[0] = f2tf32(kv.x); pk[2] = f2tf32(kv.y);
            pk[4] = f2tf32(kv.z); pk[6] = f2tf32(kv.w);
            float4 vv = *(const float4*)&Vp[(size_t)(kt * 64 + r) * Cc + c4];
            *(uint4*)&Vs[r * FST + c4] =
                make_uint4(f2tf32(vv.x), f2tf32(vv.y), f2tf32(vv.z), f2tf32(vv.w));
        }
        __syncthreads();

        // ---- S = Q K^T : m16 x n64, k=64
        float sacc[8][4];
#pragma unroll
        for (int nt = 0; nt < 8; nt++)
#pragma unroll
            for (int u = 0; u < 4; u++) sacc[nt][u] = 0.f;

#pragma unroll
        for (int kc = 0; kc < 8; kc++) {
            int kb = kc * 8;
#pragma unroll
            for (int nt = 0; nt < 8; nt++) {
                uint2 bu = *(uint2*)&Ks[(nt * 8 + g) * FST + kb + 2*t];
                unsigned bb[2] = {bu.x, bu.y};
                mma_tf32(sacc[nt], qa[kc], bb);
            }
        }

        // ---- online softmax rows r=0 (g), r=1 (g+8)
#pragma unroll
        for (int r = 0; r < 2; r++) {
            float mloc = -INFINITY;
#pragma unroll
            for (int nt = 0; nt < 8; nt++)
                mloc = fmaxf(mloc, fmaxf(sacc[nt][2*r], sacc[nt][2*r+1]));
            mloc = fmaxf(mloc, __shfl_xor_sync(0xffffffffu, mloc, 1));
            mloc = fmaxf(mloc, __shfl_xor_sync(0xffffffffu, mloc, 2));
            float mnew = fmaxf(mrow[r], mloc * QSCALE);
            float alpha = __expf(mrow[r] - mnew);
            float sum = 0.f;
#pragma unroll
            for (int nt = 0; nt < 8; nt++) {
#pragma unroll
                for (int j = 0; j < 2; j++) {
                    float p = __expf(sacc[nt][2*r+j] * QSCALE - mnew);
                    sacc[nt][2*r+j] = p;
                    sum += p;
                }
            }
            sum += __shfl_xor_sync(0xffffffffu, sum, 1);
            sum += __shfl_xor_sync(0xffffffffu, sum, 2);
            lrow[r] = lrow[r] * alpha + sum;
            mrow[r] = mnew;
#pragma unroll
            for (int dt = 0; dt < 8; dt++) {
                oacc[dt][2*r]   *= alpha;
                oacc[dt][2*r+1] *= alpha;
            }
        }

        // ---- write P (permuted), warp-local rows only
        {
            int r0 = wq + g, r1 = r0 + 8;
#pragma unroll
            for (int nt = 0; nt < 8; nt++) {
                Ps[r0 * FST + nt*8 + p0] = f2tf32(sacc[nt][0]);
                Ps[r0 * FST + nt*8 + p1] = f2tf32(sacc[nt][1]);
                Ps[r1 * FST + nt*8 + p0] = f2tf32(sacc[nt][2]);
                Ps[r1 * FST + nt*8 + p1] = f2tf32(sacc[nt][3]);
            }
        }
        __syncwarp();

        // ---- O += P V : m16 x n64(d), k=64(keys)
#pragma unroll
        for (int kc = 0; kc < 8; kc++) {
            int kb = kc * 8;
            unsigned pa[4];
            uint2 lo = *(uint2*)&Ps[(wq + g)     * FST + kb + 2*t];
            uint2 hi = *(uint2*)&Ps[(wq + g + 8) * FST + kb + 2*t];
            pa[0] = lo.x; pa[1] = hi.x; pa[2] = lo.y; pa[3] = hi.y;
#pragma unroll
            for (int dt = 0; dt < 8; dt++) {
                unsigned bb[2];
                bb[0] = Vs[(kb + t)     * FST + dt*8 + g];
                bb[1] = Vs[(kb + t + 4) * FST + dt*8 + g];
                mma_tf32(oacc[dt], pa, bb);
            }
        }
        __syncthreads();   // before next tile overwrites Ks/Vs
    }

    // ---- epilogue
#pragma unroll
    for (int r = 0; r < 2; r++) {
        float inv = 1.f / lrow[r];
        int grow = b * Sc + qt * 128 + wq + g + 8*r;
#pragma unroll
        for (int dt = 0; dt < 8; dt++) {
            int col = h * Dc + dt * 8 + 2 * t;
            float2 v = make_float2(oacc[dt][2*r] * inv, oacc[dt][2*r+1] * inv);
            *(float2*)&Og[(size_t)grow * Cc + col] = v;
        }
    }
}

// ------------------------- launch -------------------------------------------
extern "C" void kernel_launch(void* const* d_in, const int* in_sizes, int n_in,
                              void* d_out, int out_size) {
    const float* x  = (const float*)d_in[0];
    const float* Wq = (const float*)d_in[1];
    const float* Wk = (const float*)d_in[2];
    const float* Wv = (const float*)d_in[3];
    const float* Wo = (const float*)d_in[4];
    const float* bo = (const float*)d_in[5];
    const float* Aq = (const float*)d_in[6];
    const float* Bq = (const float*)d_in[7];
    const float* Ak = (const float*)d_in[8];
    const float* Bk = (const float*)d_in[9];
    const float* Av = (const float*)d_in[10];
    const float* Bv = (const float*)d_in[11];
    const float* Ao = (const float*)d_in[12];
    const float* Bo = (const float*)d_in[13];
    float* out = (float*)d_out;

    float *pWq, *pWk, *pWv, *pWo, *pq, *pk, *pv, *po;
    cudaGetSymbolAddress((void**)&pWq, g_Wq);
    cudaGetSymbolAddress((void**)&pWk, g_Wk);
    cudaGetSymbolAddress((void**)&pWv, g_Wv);
    cudaGetSymbolAddress((void**)&pWo, g_Wo);
    cudaGetSymbolAddress((void**)&pq, g_q);
    cudaGetSymbolAddress((void**)&pk, g_k);
    cudaGetSymbolAddress((void**)&pv, g_v);
    cudaGetSymbolAddress((void**)&po, g_oacc);

    // 1) fold LoRA into dense weights
    dim3 fgrid((Cc * Cc + 255) / 256, 4);
    fuse_all_kernel<<<fgrid, 256>>>(Wq, Aq, Bq, Wk, Ak, Bk, Wv, Av, Bv, Wo, Ao, Bo,
                                    pWq, pWk, pWv, pWo);

    // 2) q/k/v projections in one launch
    dim3 ggrid(Cc / 128, Mrows / 128, 3);
    gemm_tf32_kernel<<<ggrid, 256>>>(x, pWq, pWk, pWv, nullptr, pq, pk, pv,
                                     Mrows, Cc, Cc);

    // 3) flash attention
    cudaFuncSetAttribute(flash_tf32_kernel,
                         cudaFuncAttributeMaxDynamicSharedMemorySize, FLASH_SMEM);
    dim3 agrid(Sc / 128, Hc, Bc);           // (16, 20, 2)
    flash_tf32_kernel<<<agrid, 256, FLASH_SMEM>>>(pq, pk, pv, po);

    // 4) output projection (+bias) -> d_out
    dim3 ogrid(Cc / 128, Mrows / 128, 1);
    gemm_tf32_kernel<<<ogrid, 256>>>(po, pWo, pWo, pWo, bo, out, out, out,
                                     Mrows, Cc, Cc);
}

// round 5
// speedup vs baseline: 1.2998x; 1.1594x over previous
#include <cuda_runtime.h>
#include <cuda_bf16.h>
#include <math.h>

// Problem constants
#define Bc 2
#define Sc 2048
#define Cc 1280
#define Hc 20
#define Dc 64
#define Rc 16
#define Mrows (Bc*Sc)          // 4096
#define QSCALE 0.125f          // 1/sqrt(64)
#define SC2 (0.125f * 1.44269504088896f)   // QSCALE * log2(e)

// ------------------------- device scratch (no allocs allowed) ---------------
__device__ float g_Wq[Cc*Cc];
__device__ float g_Wk[Cc*Cc];
__device__ float g_Wv[Cc*Cc];
__device__ float g_Wo[Cc*Cc];
__device__ float g_q[Mrows*Cc];     // tf32 bits, col-permuted
__device__ float g_k[Mrows*Cc];     // tf32 bits, col-permuted
__device__ float g_v[Mrows*Cc];     // tf32 bits, V^T layout [b][h][64][2048], s-permuted
__device__ float g_oacc[Mrows*Cc];  // plain fp32

// ------------------------- helpers ------------------------------------------
__device__ __forceinline__ unsigned f2tf32(float f) {
    unsigned u;
    asm("cvt.rna.tf32.f32 %0, %1;" : "=r"(u) : "f"(f));
    return u;
}

__device__ __forceinline__ float ex2f(float x) {
    float y;
    asm("ex2.approx.f32 %0, %1;" : "=f"(y) : "f"(x));
    return y;
}

__device__ __forceinline__ void mma_tf32(float* d, const unsigned* a, const unsigned* b) {
    asm("mma.sync.aligned.m16n8k8.row.col.f32.tf32.tf32.f32 "
        "{%0,%1,%2,%3}, {%4,%5,%6,%7}, {%8,%9}, {%0,%1,%2,%3};"
        : "+f"(d[0]), "+f"(d[1]), "+f"(d[2]), "+f"(d[3])
        : "r"(a[0]), "r"(a[1]), "r"(a[2]), "r"(a[3]), "r"(b[0]), "r"(b[1]));
}

__device__ __forceinline__ void cp_async16(unsigned s, const void* g) {
    asm volatile("cp.async.cg.shared.global [%0], [%1], 16;" :: "r"(s), "l"(g));
}
#define CP_COMMIT() asm volatile("cp.async.commit_group;")
#define CP_WAIT0()  asm volatile("cp.async.wait_group 0;" ::: "memory")

// ------------------------- fuse LoRA into dense weights ----------------------
__global__ void fuse_all_kernel(
    const float* __restrict__ Wq, const float* __restrict__ Aq, const float* __restrict__ Bq,
    const float* __restrict__ Wk, const float* __restrict__ Ak, const float* __restrict__ Bk,
    const float* __restrict__ Wv, const float* __restrict__ Av, const float* __restrict__ Bv,
    const float* __restrict__ Wo, const float* __restrict__ Ao, const float* __restrict__ Bo,
    float* __restrict__ oq, float* __restrict__ ok,
    float* __restrict__ ov, float* __restrict__ oo) {
    int idx = blockIdx.x * blockDim.x + threadIdx.x;
    if (idx >= Cc*Cc) return;
    const float *W, *A, *Bup; float* out;
    switch (blockIdx.y) {
        case 0: W = Wq; A = Aq; Bup = Bq; out = oq; break;
        case 1: W = Wk; A = Ak; Bup = Bk; out = ok; break;
        case 2: W = Wv; A = Av; Bup = Bv; out = ov; break;
        default: W = Wo; A = Ao; Bup = Bo; out = oo; break;
    }
    int o = idx / Cc;
    int c = idx - o * Cc;
    float acc = W[idx];
#pragma unroll
    for (int r = 0; r < Rc; r++)
        acc += Bup[o*Rc + r] * A[r*Cc + c];
    out[idx] = acc;
}

// ------------------------- tf32 GEMM: Y = X @ W^T (+bias / fancy epilogue) ---
// mode 0: plain fp32 out (+bias). mode 1: tf32 bits, cols permuted within
// 8-groups (for Q/K fragment LDS.64). mode 2: tf32 bits, written as V^T
// [b][h][d][s] with s permuted within 8-groups.
#define XST 36
__global__ __launch_bounds__(256) void gemm_tf32_kernel(
    const float* __restrict__ X,
    const float* __restrict__ W0, const float* __restrict__ W1, const float* __restrict__ W2,
    const float* __restrict__ bias,
    float* __restrict__ Y0, float* __restrict__ Y1, float* __restrict__ Y2,
    int M, int N, int K, int md0, int md1, int md2) {
    __shared__ unsigned Xs[128 * XST];
    __shared__ unsigned Ws[128 * XST];

    const float* W = (blockIdx.z == 0) ? W0 : (blockIdx.z == 1) ? W1 : W2;
    float* Y       = (blockIdx.z == 0) ? Y0 : (blockIdx.z == 1) ? Y1 : Y2;
    int mode       = (blockIdx.z == 0) ? md0 : (blockIdx.z == 1) ? md1 : md2;

    int tid = threadIdx.x;
    int lane = tid & 31, wid = tid >> 5;
    int g = lane >> 2, t = lane & 3;
    int wm = wid & 1, wn = wid >> 1;
    int m0 = blockIdx.y * 128, n0 = blockIdx.x * 128;

    float acc[4][4][4];
#pragma unroll
    for (int i = 0; i < 4; i++)
#pragma unroll
        for (int j = 0; j < 4; j++)
#pragma unroll
            for (int u = 0; u < 4; u++) acc[i][j][u] = 0.f;

    for (int k0 = 0; k0 < K; k0 += 32) {
#pragma unroll
        for (int e = tid; e < 128 * 8; e += 256) {
            int r = e >> 3, c4 = (e & 7) << 2;
            float4 xv = *(const float4*)&X[(size_t)(m0 + r) * K + k0 + c4];
            unsigned* p = &Xs[r * XST + c4];
            p[0] = f2tf32(xv.x); p[1] = f2tf32(xv.y);
            p[2] = f2tf32(xv.z); p[3] = f2tf32(xv.w);
            float4 wv = *(const float4*)&W[(size_t)(n0 + r) * K + k0 + c4];
            unsigned* q = &Ws[r * XST + c4];
            q[0] = f2tf32(wv.x); q[1] = f2tf32(wv.y);
            q[2] = f2tf32(wv.z); q[3] = f2tf32(wv.w);
        }
        __syncthreads();

#pragma unroll
        for (int kc = 0; kc < 4; kc++) {
            int kb = kc * 8;
            unsigned a[4][4], b[4][2];
#pragma unroll
            for (int mt = 0; mt < 4; mt++) {
                int rb = wm * 64 + mt * 16;
                a[mt][0] = Xs[(rb + g)     * XST + kb + t];
                a[mt][1] = Xs[(rb + g + 8) * XST + kb + t];
                a[mt][2] = Xs[(rb + g)     * XST + kb + t + 4];
                a[mt][3] = Xs[(rb + g + 8) * XST + kb + t + 4];
            }
#pragma unroll
            for (int nt = 0; nt < 4; nt++) {
                int nb = wn * 32 + nt * 8;
                b[nt][0] = Ws[(nb + g) * XST + kb + t];
                b[nt][1] = Ws[(nb + g) * XST + kb + t + 4];
            }
#pragma unroll
            for (int mt = 0; mt < 4; mt++)
#pragma unroll
                for (int nt = 0; nt < 4; nt++)
                    mma_tf32(acc[mt][nt], a[mt], b[nt]);
        }
        __syncthreads();
    }

    if (mode == 0) {
#pragma unroll
        for (int mt = 0; mt < 4; mt++) {
            int row = m0 + wm * 64 + mt * 16 + g;
#pragma unroll
            for (int nt = 0; nt < 4; nt++) {
                int col = n0 + wn * 32 + nt * 8 + 2 * t;
                float b0 = bias ? bias[col] : 0.f;
                float b1 = bias ? bias[col + 1] : 0.f;
                float2 v0 = make_float2(acc[mt][nt][0] + b0, acc[mt][nt][1] + b1);
                float2 v1 = make_float2(acc[mt][nt][2] + b0, acc[mt][nt][3] + b1);
                *(float2*)&Y[(size_t)row * N + col] = v0;
                *(float2*)&Y[(size_t)(row + 8) * N + col] = v1;
            }
        }
    } else if (mode == 1) {
        unsigned* Yu = (unsigned*)Y;
#pragma unroll
        for (int mt = 0; mt < 4; mt++) {
            int r0 = m0 + wm * 64 + mt * 16 + g, r1 = r0 + 8;
#pragma unroll
            for (int nt = 0; nt < 4; nt++) {
                int colb = n0 + wn * 32 + nt * 8;
#pragma unroll
                for (int j = 0; j < 2; j++) {
                    int lc = 2 * t + j;
                    int pc = 2 * (lc & 3) + ((lc >> 2) & 1);
                    Yu[(size_t)r0 * N + colb + pc] = f2tf32(acc[mt][nt][j]);
                    Yu[(size_t)r1 * N + colb + pc] = f2tf32(acc[mt][nt][2 + j]);
                }
            }
        }
    } else {
        // V^T: out[((b*Hc + h)*Dc + d)*Sc + s_perm] = tf32(v[row][col])
        unsigned* Yu = (unsigned*)Y;
#pragma unroll
        for (int mt = 0; mt < 4; mt++) {
            int rr[2];
            rr[0] = m0 + wm * 64 + mt * 16 + g; rr[1] = rr[0] + 8;
#pragma unroll
            for (int ri = 0; ri < 2; ri++) {
                int bb = rr[ri] >> 11;
                int s = rr[ri] & 2047;
                int sp = (s & ~7) | (2 * (s & 3) + ((s >> 2) & 1));
#pragma unroll
                for (int nt = 0; nt < 4; nt++) {
#pragma unroll
                    for (int j = 0; j < 2; j++) {
                        int col = n0 + wn * 32 + nt * 8 + 2 * t + j;
                        int h = col >> 6, d = col & 63;
                        Yu[(size_t)((bb * Hc + h) * Dc + d) * Sc + sp] =
                            f2tf32(acc[mt][nt][ri * 2 + j]);
                    }
                }
            }
        }
    }
}

// ------------------------- tf32 flash attention ------------------------------
// grid (S/128, H, B) = (16,20,2); 256 threads = 8 warps; warp owns 16 q-rows.
// All inputs pre-converted tf32 + pre-permuted. cp.async double-buffered K/VT.
#define FST 72
#define KB_W (64*FST)                       // words per K or V buffer
#define FLASH_SMEM ((4*KB_W + 128*FST) * 4) // 2xK + 2xVT + P = 110592 B

__global__ __launch_bounds__(256, 2) void flash_tf32_kernel(
    const unsigned* __restrict__ Qg, const unsigned* __restrict__ Kg,
    const unsigned* __restrict__ VTg, float* __restrict__ Og) {
    extern __shared__ unsigned sm[];
    unsigned* Ps = sm + 4 * KB_W;          // 128 x 72 (P; Q staging first)

    int tid = threadIdx.x;
    int lane = tid & 31, wid = tid >> 5;
    int g = lane >> 2, t = lane & 3;
    int wq = wid * 16;
    int qt = blockIdx.x, h = blockIdx.y, b = blockIdx.z;

    unsigned smem_base = (unsigned)__cvta_generic_to_shared(sm);

    const unsigned* Qp  = Qg + (size_t)(b * Sc + qt * 128) * Cc + h * Dc;
    const unsigned* Kp  = Kg + (size_t)b * Sc * Cc + h * Dc;
    const unsigned* VTp = VTg + (size_t)(b * Hc + h) * Dc * Sc;

    // ---- kick off fill of tile 0 into buffer 0
    {
        unsigned sK = smem_base;
        unsigned sV = smem_base + 2 * KB_W * 4;
#pragma unroll
        for (int i = 0; i < 4; i++) {
            int e = tid + i * 256;
            int r = e >> 4, c4 = (e & 15) << 2;
            cp_async16(sK + (r * FST + c4) * 4, Kp + (size_t)r * Cc + c4);
            cp_async16(sV + (r * FST + c4) * 4, VTp + (size_t)r * Sc + c4);
        }
        CP_COMMIT();
    }

    // ---- stage Q (128x64, already tf32+permuted) into Ps, lift to registers
#pragma unroll
    for (int e = tid; e < 128 * 16; e += 256) {
        int r = e >> 4, c4 = (e & 15) << 2;
        *(uint4*)&Ps[r * FST + c4] = *(const uint4*)&Qp[(size_t)r * Cc + c4];
    }
    __syncthreads();

    unsigned qa[8][4];
#pragma unroll
    for (int kc = 0; kc < 8; kc++) {
        int kb = kc * 8;
        uint2 lo = *(uint2*)&Ps[(wq + g)     * FST + kb + 2*t];
        uint2 hi = *(uint2*)&Ps[(wq + g + 8) * FST + kb + 2*t];
        qa[kc][0] = lo.x; qa[kc][1] = hi.x; qa[kc][2] = lo.y; qa[kc][3] = hi.y;
    }
    __syncthreads();   // Ps free for P use

    int p0 = (t & 1) * 4 + (t >> 1);
    int p1 = p0 + 2;

    float mrow[2] = {-INFINITY, -INFINITY};
    float lrow[2] = {0.f, 0.f};
    float oacc[8][4];
#pragma unroll
    for (int dt = 0; dt < 8; dt++)
#pragma unroll
        for (int u = 0; u < 4; u++) oacc[dt][u] = 0.f;

    const int NT = Sc / 64;   // 32
    for (int kt = 0; kt < NT; kt++) {
        CP_WAIT0();
        __syncthreads();   // fills visible to all; all done with prev compute

        // prefetch next tile into the other buffer
        if (kt + 1 < NT) {
            int alt = (kt + 1) & 1;
            unsigned sK = smem_base + alt * KB_W * 4;
            unsigned sV = smem_base + (2 + alt) * KB_W * 4;
            const unsigned* Kn  = Kp + (size_t)(kt + 1) * 64 * Cc;
            const unsigned* VTn = VTp + (kt + 1) * 64;
#pragma unroll
            for (int i = 0; i < 4; i++) {
                int e = tid + i * 256;
                int r = e >> 4, c4 = (e & 15) << 2;
                cp_async16(sK + (r * FST + c4) * 4, Kn + (size_t)r * Cc + c4);
                cp_async16(sV + (r * FST + c4) * 4, VTn + (size_t)r * Sc + c4);
            }
            CP_COMMIT();
        }

        unsigned* Ks = sm + (kt & 1) * KB_W;
        unsigned* Vs = sm + (2 + (kt & 1)) * KB_W;

        // ---- S = Q K^T : m16 x n64, k=64
        float sacc[8][4];
#pragma unroll
        for (int nt = 0; nt < 8; nt++)
#pragma unroll
            for (int u = 0; u < 4; u++) sacc[nt][u] = 0.f;

#pragma unroll
        for (int kc = 0; kc < 8; kc++) {
            int kb = kc * 8;
#pragma unroll
            for (int nt = 0; nt < 8; nt++) {
                uint2 bu = *(uint2*)&Ks[(nt * 8 + g) * FST + kb + 2*t];
                unsigned bbf[2] = {bu.x, bu.y};
                mma_tf32(sacc[nt], qa[kc], bbf);
            }
        }

        // ---- online softmax (base-2 domain), rows r=0 (g), r=1 (g+8)
#pragma unroll
        for (int r = 0; r < 2; r++) {
            float mloc = -INFINITY;
#pragma unroll
            for (int nt = 0; nt < 8; nt++)
                mloc = fmaxf(mloc, fmaxf(sacc[nt][2*r], sacc[nt][2*r+1]));
            mloc = fmaxf(mloc, __shfl_xor_sync(0xffffffffu, mloc, 1));
            mloc = fmaxf(mloc, __shfl_xor_sync(0xffffffffu, mloc, 2));
            float mnew = fmaxf(mrow[r], mloc * SC2);
            float alpha = ex2f(mrow[r] - mnew);
            float sum = 0.f;
#pragma unroll
            for (int nt = 0; nt < 8; nt++) {
#pragma unroll
                for (int j = 0; j < 2; j++) {
                    float p = ex2f(fmaf(sacc[nt][2*r+j], SC2, -mnew));
                    sacc[nt][2*r+j] = p;
                    sum += p;
                }
            }
            sum += __shfl_xor_sync(0xffffffffu, sum, 1);
            sum += __shfl_xor_sync(0xffffffffu, sum, 2);
            lrow[r] = lrow[r] * alpha + sum;
            mrow[r] = mnew;
#pragma unroll
            for (int dt = 0; dt < 8; dt++) {
                oacc[dt][2*r]   *= alpha;
                oacc[dt][2*r+1] *= alpha;
            }
        }

        // ---- write P (permuted), warp-local rows only
        {
            int r0 = wq + g, r1 = r0 + 8;
#pragma unroll
            for (int nt = 0; nt < 8; nt++) {
                Ps[r0 * FST + nt*8 + p0] = f2tf32(sacc[nt][0]);
                Ps[r0 * FST + nt*8 + p1] = f2tf32(sacc[nt][1]);
                Ps[r1 * FST + nt*8 + p0] = f2tf32(sacc[nt][2]);
                Ps[r1 * FST + nt*8 + p1] = f2tf32(sacc[nt][3]);
            }
        }
        __syncwarp();

        // ---- O += P V : m16 x n64(d), k=64(keys). V^T rows = d, cols = keys.
#pragma unroll
        for (int kc = 0; kc < 8; kc++) {
            int kb = kc * 8;
            unsigned pa[4];
            uint2 lo = *(uint2*)&Ps[(wq + g)     * FST + kb + 2*t];
            uint2 hi = *(uint2*)&Ps[(wq + g + 8) * FST + kb + 2*t];
            pa[0] = lo.x; pa[1] = hi.x; pa[2] = lo.y; pa[3] = hi.y;
#pragma unroll
            for (int dt = 0; dt < 8; dt++) {
                uint2 bu = *(uint2*)&Vs[(dt * 8 + g) * FST + kb + 2*t];
                unsigned bbf[2] = {bu.x, bu.y};
                mma_tf32(oacc[dt], pa, bbf);
            }
        }
        // no trailing barrier: next iteration's CP_WAIT0+syncthreads covers WAR
    }

    // ---- epilogue
#pragma unroll
    for (int r = 0; r < 2; r++) {
        float inv = 1.f / lrow[r];
        int grow = b * Sc + qt * 128 + wq + g + 8*r;
#pragma unroll
        for (int dt = 0; dt < 8; dt++) {
            int col = h * Dc + dt * 8 + 2 * t;
            float2 v = make_float2(oacc[dt][2*r] * inv, oacc[dt][2*r+1] * inv);
            *(float2*)&Og[(size_t)grow * Cc + col] = v;
        }
    }
}

// ------------------------- launch -------------------------------------------
extern "C" void kernel_launch(void* const* d_in, const int* in_sizes, int n_in,
                              void* d_out, int out_size) {
    const float* x  = (const float*)d_in[0];
    const float* Wq = (const float*)d_in[1];
    const float* Wk = (const float*)d_in[2];
    const float* Wv = (const float*)d_in[3];
    const float* Wo = (const float*)d_in[4];
    const float* bo = (const float*)d_in[5];
    const float* Aq = (const float*)d_in[6];
    const float* Bq = (const float*)d_in[7];
    const float* Ak = (const float*)d_in[8];
    const float* Bk = (const float*)d_in[9];
    const float* Av = (const float*)d_in[10];
    const float* Bv = (const float*)d_in[11];
    const float* Ao = (const float*)d_in[12];
    const float* Bo = (const float*)d_in[13];
    float* out = (float*)d_out;

    float *pWq, *pWk, *pWv, *pWo, *pq, *pk, *pv, *po;
    cudaGetSymbolAddress((void**)&pWq, g_Wq);
    cudaGetSymbolAddress((void**)&pWk, g_Wk);
    cudaGetSymbolAddress((void**)&pWv, g_Wv);
    cudaGetSymbolAddress((void**)&pWo, g_Wo);
    cudaGetSymbolAddress((void**)&pq, g_q);
    cudaGetSymbolAddress((void**)&pk, g_k);
    cudaGetSymbolAddress((void**)&pv, g_v);
    cudaGetSymbolAddress((void**)&po, g_oacc);

    // 1) fold LoRA into dense weights
    dim3 fgrid((Cc * Cc + 255) / 256, 4);
    fuse_all_kernel<<<fgrid, 256>>>(Wq, Aq, Bq, Wk, Ak, Bk, Wv, Av, Bv, Wo, Ao, Bo,
                                    pWq, pWk, pWv, pWo);

    // 2) q/k/v projections; q,k -> tf32 permuted; v -> tf32 V^T (s-permuted)
    dim3 ggrid(Cc / 128, Mrows / 128, 3);
    gemm_tf32_kernel<<<ggrid, 256>>>(x, pWq, pWk, pWv, nullptr, pq, pk, pv,
                                     Mrows, Cc, Cc, 1, 1, 2);

    // 3) flash attention (cp.async double-buffered, pre-converted operands)
    cudaFuncSetAttribute(flash_tf32_kernel,
                         cudaFuncAttributeMaxDynamicSharedMemorySize, FLASH_SMEM);
    dim3 agrid(Sc / 128, Hc, Bc);           // (16, 20, 2)
    flash_tf32_kernel<<<agrid, 256, FLASH_SMEM>>>(
        (const unsigned*)pq, (const unsigned*)pk, (const unsigned*)pv, po);

    // 4) output projection (+bias) -> d_out
    dim3 ogrid(Cc / 128, Mrows / 128, 1);
    gemm_tf32_kernel<<<ogrid, 256>>>(po, pWo, pWo, pWo, bo, out, out, out,
                                     Mrows, Cc, Cc, 0, 0, 0);
}